// round 8
// baseline (speedup 1.0000x reference)
#include <cuda_runtime.h>
#include <cstdint>

// HashEmbedding: B*L=819200 tokens, H=2, E=64, out=[emb(64), pv0, pv1] f32
// d_in: words int32[819200], hash_table int32[1000000,2],
//       W f32[100000,64], P f32[1000000,2]

static constexpr int NTOK  = 16384 * 50;   // 819200
static constexpr int EMBED = 64;
static constexpr int OUTW  = EMBED + 2;    // 66
static constexpr int TPW   = 8;            // tokens per warp
static constexpr int TPB   = 256;

// minBlocksPerMultiprocessor=4 -> ~64-reg budget: lets ptxas keep the full
// 16-load landing window live instead of folding it to ~8 at 32 regs.
__global__ void __launch_bounds__(TPB, 4)
hash_embedding_kernel(const int*    __restrict__ words,
                      const int2*   __restrict__ hash_table,
                      const float*  __restrict__ W,
                      const float2* __restrict__ P2,
                      float*        __restrict__ out)
{
    const int warp = (blockIdx.x * blockDim.x + threadIdx.x) >> 5;
    const int lane = threadIdx.x & 31;
    const int base = warp * TPW;
    if (base >= NTOK) return;
    const float* Pf = reinterpret_cast<const float*>(P2);

    // ---- Distributed scalar phase: lane t (mod 8) owns token base+t.
    // Replicated addresses dedup in-warp: one LDG per stage covers 8 tokens. ----
    const int    tok = base + (lane & 7);
    const int    w   = __ldg(&words[tok]);
    const int2   h   = __ldg(&hash_table[w]);
    const float2 pwv = __ldg(&P2[w]);

    if (lane < TPW) {
        float2 pv;
        pv.x = __ldg(&Pf[(size_t)h.x * 2 + 0]);
        pv.y = __ldg(&Pf[(size_t)h.y * 2 + 1]);
        *reinterpret_cast<float2*>(out + (size_t)tok * OUTW + EMBED) = pv;
    }

    // ---- Resolve all row indices first (SHFL, ALU pipe), then burst-issue
    // all 16 W-row gathers back-to-back: maximal MLP, no consume interleave. ----
    int hx[TPW], hy[TPW];
#pragma unroll
    for (int t = 0; t < TPW; t++) {
        hx[t] = __shfl_sync(0xffffffffu, h.x, t);
        hy[t] = __shfl_sync(0xffffffffu, h.y, t);
    }

    float2 a[TPW], b[TPW];
#pragma unroll
    for (int t = 0; t < TPW; t++) {
        a[t] = __ldg(reinterpret_cast<const float2*>(W + (size_t)hx[t] * EMBED) + lane);
        b[t] = __ldg(reinterpret_cast<const float2*>(W + (size_t)hy[t] * EMBED) + lane);
    }

    // ---- Consume in order, store. ----
#pragma unroll
    for (int t = 0; t < TPW; t++) {
        const float px = __shfl_sync(0xffffffffu, pwv.x, t);
        const float py = __shfl_sync(0xffffffffu, pwv.y, t);
        float2 e;
        e.x = fmaf(a[t].x, px, b[t].x * py);
        e.y = fmaf(a[t].y, px, b[t].y * py);
        float* o = out + (size_t)(base + t) * OUTW;   // 264B stride, 8B aligned
        reinterpret_cast<float2*>(o)[lane] = e;       // cols 0..63
    }
}

extern "C" void kernel_launch(void* const* d_in, const int* in_sizes, int n_in,
                              void* d_out, int out_size)
{
    const int*    words      = (const int*)d_in[0];
    const int2*   hash_table = (const int2*)d_in[1];
    const float*  W          = (const float*)d_in[2];
    const float2* P          = (const float2*)d_in[3];
    float*        out        = (float*)d_out;

    const int tokens_per_block = (TPB / 32) * TPW;                        // 64
    const int blocks = (NTOK + tokens_per_block - 1) / tokens_per_block;  // 12800
    hash_embedding_kernel<<<blocks, TPB>>>(words, hash_table, W, P, out);
}